// round 1
// baseline (speedup 1.0000x reference)
#include <cuda_runtime.h>
#include <cstdint>

#define SEQ   4096
#define VECT  300
#define HID   128
#define G3    384
#define NSTACK 3

typedef unsigned long long ull;
typedef long long ll;

// ---------------------------------------------------------------------------
// Scratch (static device globals — allocation-free)
// ---------------------------------------------------------------------------
__device__ float g_x   [2 * SEQ * VECT];   // original inputs (residual source)
__device__ float g_cur [2 * SEQ * VECT];   // running "out" per stack
__device__ float g_q   [2 * SEQ * VECT];
__device__ float g_k   [2 * SEQ * VECT];
__device__ float g_v   [2 * SEQ * VECT];
__device__ float g_attn[2 * SEQ * VECT];
__device__ float g_h   [2 * SEQ * VECT];
__device__ float g_tmp [2 * SEQ * VECT];
__device__ float g_scores[2ll * SEQ * SEQ];     // [2, 4096, 4096]
__device__ float g_gx  [2 * SEQ * G3];          // GRU input projections
__device__ float g_hcat[2 * HID];               // final hidden states

// ---------------------------------------------------------------------------
// Init: copy x1, x2 into g_x and g_cur
// ---------------------------------------------------------------------------
__global__ void init_kernel(const float* __restrict__ x1, const float* __restrict__ x2)
{
    int i = blockIdx.x * blockDim.x + threadIdx.x;
    const int n = SEQ * VECT;
    if (i < n) {
        float v = x1[i];
        g_x[i] = v; g_cur[i] = v;
    } else if (i < 2 * n) {
        float v = x2[i - n];
        g_x[i] = v; g_cur[i] = v;
    }
}

// ---------------------------------------------------------------------------
// Generic tiled fp32 GEMM.
//   BT=true : C[M,N] = alpha * A[M,K] * B[N,K]^T (+ bias[n])
//   BT=false: C[M,N] = alpha * A[M,K] * B[K,N]   (+ bias[n])
// 64x64 tile, BK=16, 256 threads, 4x4 micro-tile. Requires K%4==0, N%4==0.
// ---------------------------------------------------------------------------
template<bool BT>
__global__ __launch_bounds__(256) void gemm_kernel(
    const float* __restrict__ A, const float* __restrict__ B, float* __restrict__ C,
    int M, int N, int K,
    ll sAb, ll sBb, ll sCb,
    const float* __restrict__ bias, float alpha)
{
    __shared__ float As[16][68];
    __shared__ float Bs[16][68];

    A += (ll)blockIdx.z * sAb;
    B += (ll)blockIdx.z * sBb;
    C += (ll)blockIdx.z * sCb;

    const int m0 = blockIdx.y * 64;
    const int n0 = blockIdx.x * 64;
    const int tid = threadIdx.x;
    const int tx = tid & 15, ty = tid >> 4;

    float acc[4][4] = {};

    for (int k0 = 0; k0 < K; k0 += 16) {
        {   // A tile: 64 rows x 16 cols (K-contiguous)
            int r = tid >> 2, c = (tid & 3) << 2;
            float4 v = make_float4(0.f, 0.f, 0.f, 0.f);
            if (m0 + r < M && k0 + c < K)
                v = *reinterpret_cast<const float4*>(A + (size_t)(m0 + r) * K + k0 + c);
            As[c + 0][r] = v.x; As[c + 1][r] = v.y; As[c + 2][r] = v.z; As[c + 3][r] = v.w;
        }
        if (BT) {   // B[N,K]: same pattern as A
            int r = tid >> 2, c = (tid & 3) << 2;
            float4 v = make_float4(0.f, 0.f, 0.f, 0.f);
            if (n0 + r < N && k0 + c < K)
                v = *reinterpret_cast<const float4*>(B + (size_t)(n0 + r) * K + k0 + c);
            Bs[c + 0][r] = v.x; Bs[c + 1][r] = v.y; Bs[c + 2][r] = v.z; Bs[c + 3][r] = v.w;
        } else {    // B[K,N]: 16 rows x 64 cols (N-contiguous)
            int r = tid >> 4, c = (tid & 15) << 2;
            float4 v = make_float4(0.f, 0.f, 0.f, 0.f);
            if (k0 + r < K && n0 + c < N)
                v = *reinterpret_cast<const float4*>(B + (size_t)(k0 + r) * N + n0 + c);
            *reinterpret_cast<float4*>(&Bs[r][c]) = v;
        }
        __syncthreads();

        #pragma unroll
        for (int kk = 0; kk < 16; kk++) {
            float4 a4 = *reinterpret_cast<const float4*>(&As[kk][ty * 4]);
            float4 b4 = *reinterpret_cast<const float4*>(&Bs[kk][tx * 4]);
            float av[4] = {a4.x, a4.y, a4.z, a4.w};
            float bv[4] = {b4.x, b4.y, b4.z, b4.w};
            #pragma unroll
            for (int i = 0; i < 4; i++)
                #pragma unroll
                for (int j = 0; j < 4; j++)
                    acc[i][j] += av[i] * bv[j];
        }
        __syncthreads();
    }

    #pragma unroll
    for (int i = 0; i < 4; i++) {
        int m = m0 + ty * 4 + i;
        if (m >= M) continue;
        #pragma unroll
        for (int j = 0; j < 4; j++) {
            int n = n0 + tx * 4 + j;
            if (n >= N) continue;
            float r = alpha * acc[i][j];
            if (bias) r += bias[n];
            C[(size_t)m * N + n] = r;
        }
    }
}

// ---------------------------------------------------------------------------
// Row softmax over [*, SEQ] rows of the score matrix, in place.
// grid (SEQ, 2), 256 threads; each thread owns 16 contiguous-strided values.
// ---------------------------------------------------------------------------
__device__ __forceinline__ float warp_max(float v) {
    #pragma unroll
    for (int o = 16; o > 0; o >>= 1) v = fmaxf(v, __shfl_xor_sync(0xffffffffu, v, o));
    return v;
}
__device__ __forceinline__ float warp_sum(float v) {
    #pragma unroll
    for (int o = 16; o > 0; o >>= 1) v += __shfl_xor_sync(0xffffffffu, v, o);
    return v;
}

__global__ __launch_bounds__(256) void softmax_kernel(float* __restrict__ Sm)
{
    size_t off = ((size_t)blockIdx.y * SEQ + blockIdx.x) * SEQ;
    float4* row4 = reinterpret_cast<float4*>(Sm + off);
    const int t = threadIdx.x;
    const int lane = t & 31, wid = t >> 5;

    float4 v[4];
    #pragma unroll
    for (int i = 0; i < 4; i++) v[i] = row4[t + 256 * i];

    float m = -3.4e38f;
    #pragma unroll
    for (int i = 0; i < 4; i++) {
        m = fmaxf(m, fmaxf(fmaxf(v[i].x, v[i].y), fmaxf(v[i].z, v[i].w)));
    }
    __shared__ float red[8];
    m = warp_max(m);
    if (lane == 0) red[wid] = m;
    __syncthreads();
    float bm = red[0];
    #pragma unroll
    for (int k = 1; k < 8; k++) bm = fmaxf(bm, red[k]);

    float s = 0.f;
    #pragma unroll
    for (int i = 0; i < 4; i++) {
        v[i].x = __expf(v[i].x - bm); v[i].y = __expf(v[i].y - bm);
        v[i].z = __expf(v[i].z - bm); v[i].w = __expf(v[i].w - bm);
        s += v[i].x + v[i].y + v[i].z + v[i].w;
    }
    s = warp_sum(s);
    __syncthreads();               // red reuse
    if (lane == 0) red[wid] = s;
    __syncthreads();
    float bs = 0.f;
    #pragma unroll
    for (int k = 0; k < 8; k++) bs += red[k];
    float inv = 1.f / bs;

    #pragma unroll
    for (int i = 0; i < 4; i++) {
        v[i].x *= inv; v[i].y *= inv; v[i].z *= inv; v[i].w *= inv;
        row4[t + 256 * i] = v[i];
    }
}

// ---------------------------------------------------------------------------
// dst = LayerNorm(s1 + s2) * g + b, row length 300, eps 1e-5.
// One warp per row; grid (SEQ/4, 2), 128 threads.
// ---------------------------------------------------------------------------
__global__ __launch_bounds__(128) void ln_add_kernel(
    const float* __restrict__ s1, const float* __restrict__ s2,
    const float* __restrict__ g, const float* __restrict__ b,
    float* __restrict__ dst)
{
    const int wid = threadIdx.x >> 5, lane = threadIdx.x & 31;
    const int row = blockIdx.x * 4 + wid;
    const size_t base = ((size_t)blockIdx.y * SEQ + row) * VECT;

    float v[10];
    float s = 0.f;
    #pragma unroll
    for (int i = 0; i < 10; i++) {
        int j = lane + 32 * i;
        float x = 0.f;
        if (j < VECT) x = s1[base + j] + s2[base + j];
        v[i] = x; s += x;
    }
    s = warp_sum(s);
    float mean = s * (1.f / VECT);

    float var = 0.f;
    #pragma unroll
    for (int i = 0; i < 10; i++) {
        int j = lane + 32 * i;
        if (j < VECT) { float d = v[i] - mean; var += d * d; }
    }
    var = warp_sum(var) * (1.f / VECT);
    float inv = rsqrtf(var + 1e-5f);

    #pragma unroll
    for (int i = 0; i < 10; i++) {
        int j = lane + 32 * i;
        if (j < VECT) dst[base + j] = g[j] * (v[i] - mean) * inv + b[j];
    }
}

// ---------------------------------------------------------------------------
// GRU recurrence. 2 blocks (one per GRU), 384 threads.
// Thread t owns w_hh row t in registers (packed f32x2 pairs); h lives in SMEM.
// Per step: gh_t = dot(w_t, h) + bhh_t via FFMA2, then threads 0..127 apply
// the gate nonlinearity and update h.
// ---------------------------------------------------------------------------
__global__ __launch_bounds__(384, 1) void gru_kernel(
    const float* __restrict__ whh1, const float* __restrict__ bhh1,
    const float* __restrict__ whh2, const float* __restrict__ bhh2)
{
    const int b = blockIdx.x;
    const float* whh = b ? whh2 : whh1;
    const float* bhh = b ? bhh2 : bhh1;
    const float* gx  = g_gx + (size_t)b * SEQ * G3;
    const int t = threadIdx.x;

    ull wp[64];
    const ull* w2 = reinterpret_cast<const ull*>(whh + t * HID);
    #pragma unroll
    for (int j = 0; j < 64; j++) wp[j] = w2[j];
    const float bh = bhh[t];

    __shared__ __align__(16) float hsh[HID];
    __shared__ float gsh[G3];
    float hcur = 0.f;
    if (t < HID) hsh[t] = 0.f;
    __syncthreads();

    for (int step = 0; step < SEQ; step++) {
        float xr = 0.f, xz = 0.f, xn = 0.f;
        if (t < HID) {
            const float* gr = gx + (size_t)step * G3;
            xr = gr[t]; xz = gr[t + HID]; xn = gr[t + 2 * HID];
        }

        ull a0 = 0ull, a1 = 0ull;
        const ulonglong2* h2 = reinterpret_cast<const ulonglong2*>(hsh);
        #pragma unroll
        for (int j = 0; j < 32; j++) {
            ulonglong2 hv = h2[j];
            asm("fma.rn.f32x2 %0, %1, %2, %0;" : "+l"(a0) : "l"(wp[2 * j]),     "l"(hv.x));
            asm("fma.rn.f32x2 %0, %1, %2, %0;" : "+l"(a1) : "l"(wp[2 * j + 1]), "l"(hv.y));
        }
        float lo0, hi0, lo1, hi1;
        asm("mov.b64 {%0,%1}, %2;" : "=f"(lo0), "=f"(hi0) : "l"(a0));
        asm("mov.b64 {%0,%1}, %2;" : "=f"(lo1), "=f"(hi1) : "l"(a1));
        gsh[t] = lo0 + hi0 + lo1 + hi1 + bh;
        __syncthreads();

        if (t < HID) {
            float r = 1.f / (1.f + __expf(-(xr + gsh[t])));
            float z = 1.f / (1.f + __expf(-(xz + gsh[t + HID])));
            float n = tanhf(xn + r * gsh[t + 2 * HID]);
            hcur = (1.f - z) * n + z * hcur;
            hsh[t] = hcur;
        }
        __syncthreads();
    }
    if (t < HID) g_hcat[b * HID + t] = hcur;
}

// ---------------------------------------------------------------------------
// Head: h=[256] -> relu(fc1) -> fc2 -> log_softmax -> out[3]
// ---------------------------------------------------------------------------
__global__ __launch_bounds__(256) void head_kernel(
    const float* __restrict__ fc1_w, const float* __restrict__ fc1_b,
    const float* __restrict__ fc2_w, const float* __restrict__ fc2_b,
    float* __restrict__ out)
{
    __shared__ float hs[256], ys[256], ls[3];
    const int t = threadIdx.x;
    hs[t] = g_hcat[t];
    __syncthreads();

    float acc = fc1_b[t];
    #pragma unroll 8
    for (int j = 0; j < 256; j++) acc += fc1_w[t * 256 + j] * hs[j];
    ys[t] = fmaxf(acc, 0.f);
    __syncthreads();

    if (t < 3) {
        float a = fc2_b[t];
        for (int j = 0; j < 256; j++) a += fc2_w[t * 256 + j] * ys[j];
        ls[t] = a;
    }
    __syncthreads();

    if (t == 0) {
        float m = fmaxf(ls[0], fmaxf(ls[1], ls[2]));
        float s = expf(ls[0] - m) + expf(ls[1] - m) + expf(ls[2] - m);
        float lse = m + logf(s);
        out[0] = ls[0] - lse; out[1] = ls[1] - lse; out[2] = ls[2] - lse;
    }
}

// ---------------------------------------------------------------------------
// Launch sequence
// ---------------------------------------------------------------------------
extern "C" void kernel_launch(void* const* d_in, const int* in_sizes, int n_in,
                              void* d_out, int out_size)
{
    (void)in_sizes; (void)n_in; (void)out_size;

    const float* x1     = (const float*)d_in[0];
    const float* x2     = (const float*)d_in[1];
    const float* q_w    = (const float*)d_in[2];
    const float* q_b    = (const float*)d_in[3];
    const float* k_w    = (const float*)d_in[4];
    const float* k_b    = (const float*)d_in[5];
    const float* v_w    = (const float*)d_in[6];
    const float* v_b    = (const float*)d_in[7];
    const float* aln_g  = (const float*)d_in[8];
    const float* aln_b  = (const float*)d_in[9];
    const float* w_w    = (const float*)d_in[10];
    const float* w_b    = (const float*)d_in[11];
    const float* mln_g  = (const float*)d_in[12];
    const float* mln_b  = (const float*)d_in[13];
    const float* g1_wih = (const float*)d_in[14];
    const float* g1_whh = (const float*)d_in[15];
    const float* g1_bih = (const float*)d_in[16];
    const float* g1_bhh = (const float*)d_in[17];
    const float* g2_wih = (const float*)d_in[18];
    const float* g2_whh = (const float*)d_in[19];
    const float* g2_bih = (const float*)d_in[20];
    const float* g2_bhh = (const float*)d_in[21];
    const float* fc1_w  = (const float*)d_in[22];
    const float* fc1_b  = (const float*)d_in[23];
    const float* fc2_w  = (const float*)d_in[24];
    const float* fc2_b  = (const float*)d_in[25];
    float* out = (float*)d_out;

    void *pv;
    cudaGetSymbolAddress(&pv, g_x);      float* p_x      = (float*)pv;
    cudaGetSymbolAddress(&pv, g_cur);    float* p_cur    = (float*)pv;
    cudaGetSymbolAddress(&pv, g_q);      float* p_q      = (float*)pv;
    cudaGetSymbolAddress(&pv, g_k);      float* p_k      = (float*)pv;
    cudaGetSymbolAddress(&pv, g_v);      float* p_v      = (float*)pv;
    cudaGetSymbolAddress(&pv, g_attn);   float* p_attn   = (float*)pv;
    cudaGetSymbolAddress(&pv, g_h);      float* p_h      = (float*)pv;
    cudaGetSymbolAddress(&pv, g_tmp);    float* p_tmp    = (float*)pv;
    cudaGetSymbolAddress(&pv, g_scores); float* p_scores = (float*)pv;
    cudaGetSymbolAddress(&pv, g_gx);     float* p_gxb    = (float*)pv;

    const ll SV = (ll)SEQ * VECT;
    const ll SS = (ll)SEQ * SEQ;
    const float inv_scale = 0.05773502691896258f;   // 1/sqrt(300)

    init_kernel<<<(2 * SEQ * VECT + 255) / 256, 256>>>(x1, x2);

    dim3 gp(5, 64, 2);    // N=300 -> 5 tiles
    dim3 gs(64, 64, 2);   // N=4096 -> 64 tiles

    for (int s = 0; s < NSTACK; s++) {
        gemm_kernel<true><<<gp, 256>>>(p_cur, q_w, p_q, SEQ, VECT, VECT, SV, 0, SV, q_b, 1.f);
        gemm_kernel<true><<<gp, 256>>>(p_cur, k_w, p_k, SEQ, VECT, VECT, SV, 0, SV, k_b, 1.f);
        gemm_kernel<true><<<gp, 256>>>(p_cur, v_w, p_v, SEQ, VECT, VECT, SV, 0, SV, v_b, 1.f);
        gemm_kernel<true><<<gs, 256>>>(p_q, p_k, p_scores, SEQ, SEQ, VECT, SV, SV, SS,
                                       nullptr, inv_scale);
        softmax_kernel<<<dim3(SEQ, 2), 256>>>(p_scores);
        gemm_kernel<false><<<gp, 256>>>(p_scores, p_v, p_attn, SEQ, VECT, SEQ, SS, SV, SV,
                                        nullptr, 1.f);
        ln_add_kernel<<<dim3(SEQ / 4, 2), 128>>>(p_attn, p_cur, aln_g, aln_b, p_h);
        gemm_kernel<true><<<gp, 256>>>(p_h, w_w, p_tmp, SEQ, VECT, VECT, SV, 0, SV, w_b, 1.f);
        ln_add_kernel<<<dim3(SEQ / 4, 2), 128>>>(p_tmp, p_x, mln_g, mln_b, p_cur);
    }

    dim3 gg(6, 64, 1);    // N=384 -> 6 tiles
    gemm_kernel<true><<<gg, 256>>>(p_cur,      g1_wih, p_gxb,            SEQ, G3, VECT,
                                   0, 0, 0, g1_bih, 1.f);
    gemm_kernel<true><<<gg, 256>>>(p_cur + SV, g2_wih, p_gxb + SEQ * G3, SEQ, G3, VECT,
                                   0, 0, 0, g2_bih, 1.f);
    gru_kernel<<<2, 384>>>(g1_whh, g1_bhh, g2_whh, g2_bhh);
    head_kernel<<<1, 256>>>(fc1_w, fc1_b, fc2_w, fc2_b, out);
}

// round 3
// speedup vs baseline: 1.3695x; 1.3695x over previous
#include <cuda_runtime.h>
#include <cstdint>

#define SEQ   4096
#define VECT  300
#define HID   128
#define G3    384
#define NSTACK 3

typedef unsigned long long ull;
typedef long long ll;

// ---------------------------------------------------------------------------
// Scratch (static device globals — allocation-free)
// ---------------------------------------------------------------------------
__device__ float g_x   [2 * SEQ * VECT];
__device__ float g_cur [2 * SEQ * VECT];
__device__ float g_q   [2 * SEQ * VECT];
__device__ float g_k   [2 * SEQ * VECT];
__device__ float g_v   [2 * SEQ * VECT];
__device__ float g_attn[2 * SEQ * VECT];
__device__ float g_h   [2 * SEQ * VECT];
__device__ float g_tmp [2 * SEQ * VECT];
__device__ float g_scores[2ll * SEQ * SEQ];
__device__ float g_gx  [2 * SEQ * G3];
__device__ float g_hcat[2 * HID];

// ---------------------------------------------------------------------------
__global__ void init_kernel(const float* __restrict__ x1, const float* __restrict__ x2)
{
    int i = blockIdx.x * blockDim.x + threadIdx.x;
    const int n = SEQ * VECT;
    if (i < n) {
        float v = x1[i];
        g_x[i] = v; g_cur[i] = v;
    } else if (i < 2 * n) {
        float v = x2[i - n];
        g_x[i] = v; g_cur[i] = v;
    }
}

// ---------------------------------------------------------------------------
// fp32 tiled GEMM (kept for the small projection GEMMs; K=300 precision-safe)
// ---------------------------------------------------------------------------
template<bool BT>
__global__ __launch_bounds__(256) void gemm_kernel(
    const float* __restrict__ A, const float* __restrict__ B, float* __restrict__ C,
    int M, int N, int K,
    ll sAb, ll sBb, ll sCb,
    const float* __restrict__ bias, float alpha)
{
    __shared__ float As[16][68];
    __shared__ float Bs[16][68];

    A += (ll)blockIdx.z * sAb;
    B += (ll)blockIdx.z * sBb;
    C += (ll)blockIdx.z * sCb;

    const int m0 = blockIdx.y * 64;
    const int n0 = blockIdx.x * 64;
    const int tid = threadIdx.x;
    const int tx = tid & 15, ty = tid >> 4;

    float acc[4][4] = {};

    for (int k0 = 0; k0 < K; k0 += 16) {
        {
            int r = tid >> 2, c = (tid & 3) << 2;
            float4 v = make_float4(0.f, 0.f, 0.f, 0.f);
            if (m0 + r < M && k0 + c < K)
                v = *reinterpret_cast<const float4*>(A + (size_t)(m0 + r) * K + k0 + c);
            As[c + 0][r] = v.x; As[c + 1][r] = v.y; As[c + 2][r] = v.z; As[c + 3][r] = v.w;
        }
        if (BT) {
            int r = tid >> 2, c = (tid & 3) << 2;
            float4 v = make_float4(0.f, 0.f, 0.f, 0.f);
            if (n0 + r < N && k0 + c < K)
                v = *reinterpret_cast<const float4*>(B + (size_t)(n0 + r) * K + k0 + c);
            Bs[c + 0][r] = v.x; Bs[c + 1][r] = v.y; Bs[c + 2][r] = v.z; Bs[c + 3][r] = v.w;
        } else {
            int r = tid >> 4, c = (tid & 15) << 2;
            float4 v = make_float4(0.f, 0.f, 0.f, 0.f);
            if (k0 + r < K && n0 + c < N)
                v = *reinterpret_cast<const float4*>(B + (size_t)(k0 + r) * N + n0 + c);
            *reinterpret_cast<float4*>(&Bs[r][c]) = v;
        }
        __syncthreads();

        #pragma unroll
        for (int kk = 0; kk < 16; kk++) {
            float4 a4 = *reinterpret_cast<const float4*>(&As[kk][ty * 4]);
            float4 b4 = *reinterpret_cast<const float4*>(&Bs[kk][tx * 4]);
            float av[4] = {a4.x, a4.y, a4.z, a4.w};
            float bv[4] = {b4.x, b4.y, b4.z, b4.w};
            #pragma unroll
            for (int i = 0; i < 4; i++)
                #pragma unroll
                for (int j = 0; j < 4; j++)
                    acc[i][j] += av[i] * bv[j];
        }
        __syncthreads();
    }

    #pragma unroll
    for (int i = 0; i < 4; i++) {
        int m = m0 + ty * 4 + i;
        if (m >= M) continue;
        #pragma unroll
        for (int j = 0; j < 4; j++) {
            int n = n0 + tx * 4 + j;
            if (n >= N) continue;
            float r = alpha * acc[i][j];
            if (bias) r += bias[n];
            C[(size_t)m * N + n] = r;
        }
    }
}

// ---------------------------------------------------------------------------
// TF32 tensor-core GEMM (mma.sync m16n8k8), 128x128x32 tile, cp.async 2-stage.
//   BT=true : C = alpha * A[M,K] * B[N,K]^T   (QK^T)
//   BT=false: C = alpha * A[M,K] * B[K,N]     (A·V)
// fp32 accumulate. Requires K%4==0, N even.
// ---------------------------------------------------------------------------
__device__ __forceinline__ unsigned smem_u32(const void* p)
{
    return (unsigned)__cvta_generic_to_shared(p);
}
__device__ __forceinline__ void cp_async16(unsigned dst, const float* src, bool valid)
{
    int sz = valid ? 16 : 0;
    asm volatile("cp.async.cg.shared.global [%0], [%1], 16, %2;\n"
                 :: "r"(dst), "l"(src), "r"(sz));
}
__device__ __forceinline__ uint32_t f2tf(float f)
{
    uint32_t r;
    asm("cvt.rna.tf32.f32 %0, %1;" : "=r"(r) : "f"(f));
    return r;
}
__device__ __forceinline__ void mma8(float* c, const uint32_t* a, const uint32_t* b)
{
    asm volatile(
        "mma.sync.aligned.m16n8k8.row.col.f32.tf32.tf32.f32 "
        "{%0,%1,%2,%3}, {%4,%5,%6,%7}, {%8,%9}, {%0,%1,%2,%3};"
        : "+f"(c[0]), "+f"(c[1]), "+f"(c[2]), "+f"(c[3])
        : "r"(a[0]), "r"(a[1]), "r"(a[2]), "r"(a[3]), "r"(b[0]), "r"(b[1]));
}

template<bool BT>
__global__ __launch_bounds__(256) void mma_gemm(
    const float* __restrict__ A, const float* __restrict__ B, float* __restrict__ C,
    int M, int N, int K, ll sAb, ll sBb, ll sCb, float alpha)
{
    constexpr int BM = 128, BN = 128, BK = 32;
    constexpr int AP  = 36;                     // smem A row stride (conflict-free)
    constexpr int BPT = 36;                     // BT: Bs[n][k] stride
    constexpr int BPN = 136;                    // !BT: Bs[k][n] stride
    constexpr int ASZ = BM * AP;
    constexpr int BSZ = BT ? (BN * BPT) : (BK * BPN);
    constexpr int STG = ASZ + BSZ;

    extern __shared__ float sm[];
    float* AsBuf[2] = { sm,        sm + STG };
    float* BsBuf[2] = { sm + ASZ,  sm + STG + ASZ };

    A += (ll)blockIdx.z * sAb;
    B += (ll)blockIdx.z * sBb;
    C += (ll)blockIdx.z * sCb;

    const int m0 = blockIdx.y * BM, n0 = blockIdx.x * BN;
    const int tid = threadIdx.x, lane = tid & 31, warp = tid >> 5;
    const int g = lane >> 2, tg = lane & 3;
    const int wm = (warp & 1) * 64, wn = (warp >> 1) * 32;

    float acc[4][4][4] = {};
    const int nk = (K + BK - 1) / BK;

    auto load_stage = [&](int s, int k0) {
        unsigned aBase = smem_u32(AsBuf[s]);
        unsigned bBase = smem_u32(BsBuf[s]);
        #pragma unroll
        for (int i = 0; i < 4; i++) {
            int idx = tid + i * 256;
            int r = idx >> 3, c = (idx & 7) * 4;
            bool v = (m0 + r < M) && (k0 + c < K);
            cp_async16(aBase + (unsigned)(r * AP + c) * 4,
                       A + (size_t)(m0 + r) * K + k0 + c, v);
        }
        if (BT) {
            #pragma unroll
            for (int i = 0; i < 4; i++) {
                int idx = tid + i * 256;
                int r = idx >> 3, c = (idx & 7) * 4;
                bool v = (n0 + r < N) && (k0 + c < K);
                cp_async16(bBase + (unsigned)(r * BPT + c) * 4,
                           B + (size_t)(n0 + r) * K + k0 + c, v);
            }
        } else {
            #pragma unroll
            for (int i = 0; i < 4; i++) {
                int idx = tid + i * 256;
                int r = idx >> 5, c = (idx & 31) * 4;
                bool v = (k0 + r < K) && (n0 + c < N);
                cp_async16(bBase + (unsigned)(r * BPN + c) * 4,
                           B + (size_t)(k0 + r) * N + n0 + c, v);
            }
        }
        asm volatile("cp.async.commit_group;");
    };

    load_stage(0, 0);

    for (int kt = 0; kt < nk; kt++) {
        int s = kt & 1;
        if (kt + 1 < nk) {
            load_stage(s ^ 1, (kt + 1) * BK);
            asm volatile("cp.async.wait_group 1;");
        } else {
            asm volatile("cp.async.wait_group 0;");
        }
        __syncthreads();

        const float* Ab = AsBuf[s];
        const float* Bb = BsBuf[s];

        #pragma unroll
        for (int kk = 0; kk < BK; kk += 8) {
            uint32_t ar[4][4];
            #pragma unroll
            for (int mt = 0; mt < 4; mt++) {
                int r = wm + mt * 16 + g;
                ar[mt][0] = f2tf(Ab[r * AP + kk + tg]);
                ar[mt][1] = f2tf(Ab[(r + 8) * AP + kk + tg]);
                ar[mt][2] = f2tf(Ab[r * AP + kk + tg + 4]);
                ar[mt][3] = f2tf(Ab[(r + 8) * AP + kk + tg + 4]);
            }
            uint32_t br[4][2];
            #pragma unroll
            for (int nt = 0; nt < 4; nt++) {
                int n = wn + nt * 8 + g;
                if (BT) {
                    br[nt][0] = f2tf(Bb[n * BPT + kk + tg]);
                    br[nt][1] = f2tf(Bb[n * BPT + kk + tg + 4]);
                } else {
                    br[nt][0] = f2tf(Bb[(kk + tg) * BPN + n]);
                    br[nt][1] = f2tf(Bb[(kk + tg + 4) * BPN + n]);
                }
            }
            #pragma unroll
            for (int mt = 0; mt < 4; mt++)
                #pragma unroll
                for (int nt = 0; nt < 4; nt++)
                    mma8(acc[mt][nt], ar[mt], br[nt]);
        }
        __syncthreads();
    }

    #pragma unroll
    for (int mt = 0; mt < 4; mt++) {
        #pragma unroll
        for (int nt = 0; nt < 4; nt++) {
            int row0 = m0 + wm + mt * 16 + g;
            int col  = n0 + wn + nt * 8 + 2 * tg;
            if (col < N) {
                if (row0 < M) {
                    float2 v = make_float2(alpha * acc[mt][nt][0], alpha * acc[mt][nt][1]);
                    *reinterpret_cast<float2*>(C + (size_t)row0 * N + col) = v;
                }
                if (row0 + 8 < M) {
                    float2 v = make_float2(alpha * acc[mt][nt][2], alpha * acc[mt][nt][3]);
                    *reinterpret_cast<float2*>(C + (size_t)(row0 + 8) * N + col) = v;
                }
            }
        }
    }
}

// ---------------------------------------------------------------------------
__device__ __forceinline__ float warp_max(float v) {
    #pragma unroll
    for (int o = 16; o > 0; o >>= 1) v = fmaxf(v, __shfl_xor_sync(0xffffffffu, v, o));
    return v;
}
__device__ __forceinline__ float warp_sum(float v) {
    #pragma unroll
    for (int o = 16; o > 0; o >>= 1) v += __shfl_xor_sync(0xffffffffu, v, o);
    return v;
}

__global__ __launch_bounds__(256) void softmax_kernel(float* __restrict__ Sm)
{
    size_t off = ((size_t)blockIdx.y * SEQ + blockIdx.x) * SEQ;
    float4* row4 = reinterpret_cast<float4*>(Sm + off);
    const int t = threadIdx.x;
    const int lane = t & 31, wid = t >> 5;

    float4 v[4];
    #pragma unroll
    for (int i = 0; i < 4; i++) v[i] = row4[t + 256 * i];

    float m = -3.4e38f;
    #pragma unroll
    for (int i = 0; i < 4; i++)
        m = fmaxf(m, fmaxf(fmaxf(v[i].x, v[i].y), fmaxf(v[i].z, v[i].w)));

    __shared__ float red[8];
    m = warp_max(m);
    if (lane == 0) red[wid] = m;
    __syncthreads();
    float bm = red[0];
    #pragma unroll
    for (int k = 1; k < 8; k++) bm = fmaxf(bm, red[k]);

    float s = 0.f;
    #pragma unroll
    for (int i = 0; i < 4; i++) {
        v[i].x = __expf(v[i].x - bm); v[i].y = __expf(v[i].y - bm);
        v[i].z = __expf(v[i].z - bm); v[i].w = __expf(v[i].w - bm);
        s += v[i].x + v[i].y + v[i].z + v[i].w;
    }
    s = warp_sum(s);
    __syncthreads();
    if (lane == 0) red[wid] = s;
    __syncthreads();
    float bs = 0.f;
    #pragma unroll
    for (int k = 0; k < 8; k++) bs += red[k];
    float inv = 1.f / bs;

    #pragma unroll
    for (int i = 0; i < 4; i++) {
        v[i].x *= inv; v[i].y *= inv; v[i].z *= inv; v[i].w *= inv;
        row4[t + 256 * i] = v[i];
    }
}

// ---------------------------------------------------------------------------
__global__ __launch_bounds__(128) void ln_add_kernel(
    const float* __restrict__ s1, const float* __restrict__ s2,
    const float* __restrict__ g, const float* __restrict__ b,
    float* __restrict__ dst)
{
    const int wid = threadIdx.x >> 5, lane = threadIdx.x & 31;
    const int row = blockIdx.x * 4 + wid;
    const size_t base = ((size_t)blockIdx.y * SEQ + row) * VECT;

    float v[10];
    float s = 0.f;
    #pragma unroll
    for (int i = 0; i < 10; i++) {
        int j = lane + 32 * i;
        float x = 0.f;
        if (j < VECT) x = s1[base + j] + s2[base + j];
        v[i] = x; s += x;
    }
    s = warp_sum(s);
    float mean = s * (1.f / VECT);

    float var = 0.f;
    #pragma unroll
    for (int i = 0; i < 10; i++) {
        int j = lane + 32 * i;
        if (j < VECT) { float d = v[i] - mean; var += d * d; }
    }
    var = warp_sum(var) * (1.f / VECT);
    float inv = rsqrtf(var + 1e-5f);

    #pragma unroll
    for (int i = 0; i < 10; i++) {
        int j = lane + 32 * i;
        if (j < VECT) dst[base + j] = g[j] * (v[i] - mean) * inv + b[j];
    }
}

// ---------------------------------------------------------------------------
__global__ __launch_bounds__(384, 1) void gru_kernel(
    const float* __restrict__ whh1, const float* __restrict__ bhh1,
    const float* __restrict__ whh2, const float* __restrict__ bhh2)
{
    const int b = blockIdx.x;
    const float* whh = b ? whh2 : whh1;
    const float* bhh = b ? bhh2 : bhh1;
    const float* gx  = g_gx + (size_t)b * SEQ * G3;
    const int t = threadIdx.x;

    ull wp[64];
    const ull* w2 = reinterpret_cast<const ull*>(whh + t * HID);
    #pragma unroll
    for (int j = 0; j < 64; j++) wp[j] = w2[j];
    const float bh = bhh[t];

    __shared__ __align__(16) float hsh[HID];
    __shared__ float gsh[G3];
    float hcur = 0.f;
    if (t < HID) hsh[t] = 0.f;
    __syncthreads();

    for (int step = 0; step < SEQ; step++) {
        float xr = 0.f, xz = 0.f, xn = 0.f;
        if (t < HID) {
            const float* gr = gx + (size_t)step * G3;
            xr = gr[t]; xz = gr[t + HID]; xn = gr[t + 2 * HID];
        }

        ull a0 = 0ull, a1 = 0ull;
        const ulonglong2* h2 = reinterpret_cast<const ulonglong2*>(hsh);
        #pragma unroll
        for (int j = 0; j < 32; j++) {
            ulonglong2 hv = h2[j];
            asm("fma.rn.f32x2 %0, %1, %2, %0;" : "+l"(a0) : "l"(wp[2 * j]),     "l"(hv.x));
            asm("fma.rn.f32x2 %0, %1, %2, %0;" : "+l"(a1) : "l"(wp[2 * j + 1]), "l"(hv.y));
        }
        float lo0, hi0, lo1, hi1;
        asm("mov.b64 {%0,%1}, %2;" : "=f"(lo0), "=f"(hi0) : "l"(a0));
        asm("mov.b64 {%0,%1}, %2;" : "=f"(lo1), "=f"(hi1) : "l"(a1));
        gsh[t] = lo0 + hi0 + lo1 + hi1 + bh;
        __syncthreads();

        if (t < HID) {
            float r = 1.f / (1.f + __expf(-(xr + gsh[t])));
            float z = 1.f / (1.f + __expf(-(xz + gsh[t + HID])));
            float n = tanhf(xn + r * gsh[t + 2 * HID]);
            hcur = (1.f - z) * n + z * hcur;
            hsh[t] = hcur;
        }
        __syncthreads();
    }
    if (t < HID) g_hcat[b * HID + t] = hcur;
}

// ---------------------------------------------------------------------------
__global__ __launch_bounds__(256) void head_kernel(
    const float* __restrict__ fc1_w, const float* __restrict__ fc1_b,
    const float* __restrict__ fc2_w, const float* __restrict__ fc2_b,
    float* __restrict__ out)
{
    __shared__ float hs[256], ys[256], ls[3];
    const int t = threadIdx.x;
    hs[t] = g_hcat[t];
    __syncthreads();

    float acc = fc1_b[t];
    #pragma unroll 8
    for (int j = 0; j < 256; j++) acc += fc1_w[t * 256 + j] * hs[j];
    ys[t] = fmaxf(acc, 0.f);
    __syncthreads();

    if (t < 3) {
        float a = fc2_b[t];
        for (int j = 0; j < 256; j++) a += fc2_w[t * 256 + j] * ys[j];
        ls[t] = a;
    }
    __syncthreads();

    if (t == 0) {
        float m = fmaxf(ls[0], fmaxf(ls[1], ls[2]));
        float s = expf(ls[0] - m) + expf(ls[1] - m) + expf(ls[2] - m);
        float lse = m + logf(s);
        out[0] = ls[0] - lse; out[1] = ls[1] - lse; out[2] = ls[2] - lse;
    }
}

// ---------------------------------------------------------------------------
extern "C" void kernel_launch(void* const* d_in, const int* in_sizes, int n_in,
                              void* d_out, int out_size)
{
    (void)in_sizes; (void)n_in; (void)out_size;

    const float* x1     = (const float*)d_in[0];
    const float* x2     = (const float*)d_in[1];
    const float* q_w    = (const float*)d_in[2];
    const float* q_b    = (const float*)d_in[3];
    const float* k_w    = (const float*)d_in[4];
    const float* k_b    = (const float*)d_in[5];
    const float* v_w    = (const float*)d_in[6];
    const float* v_b    = (const float*)d_in[7];
    const float* aln_g  = (const float*)d_in[8];
    const float* aln_b  = (const float*)d_in[9];
    const float* w_w    = (const float*)d_in[10];
    const float* w_b    = (const float*)d_in[11];
    const float* mln_g  = (const float*)d_in[12];
    const float* mln_b  = (const float*)d_in[13];
    const float* g1_wih = (const float*)d_in[14];
    const float* g1_whh = (const float*)d_in[15];
    const float* g1_bih = (const float*)d_in[16];
    const float* g1_bhh = (const float*)d_in[17];
    const float* g2_wih = (const float*)d_in[18];
    const float* g2_whh = (const float*)d_in[19];
    const float* g2_bih = (const float*)d_in[20];
    const float* g2_bhh = (const float*)d_in[21];
    const float* fc1_w  = (const float*)d_in[22];
    const float* fc1_b  = (const float*)d_in[23];
    const float* fc2_w  = (const float*)d_in[24];
    const float* fc2_b  = (const float*)d_in[25];
    float* out = (float*)d_out;

    void *pv;
    cudaGetSymbolAddress(&pv, g_x);      float* p_x      = (float*)pv;
    cudaGetSymbolAddress(&pv, g_cur);    float* p_cur    = (float*)pv;
    cudaGetSymbolAddress(&pv, g_q);      float* p_q      = (float*)pv;
    cudaGetSymbolAddress(&pv, g_k);      float* p_k      = (float*)pv;
    cudaGetSymbolAddress(&pv, g_v);      float* p_v      = (float*)pv;
    cudaGetSymbolAddress(&pv, g_attn);   float* p_attn   = (float*)pv;
    cudaGetSymbolAddress(&pv, g_h);      float* p_h      = (float*)pv;
    cudaGetSymbolAddress(&pv, g_tmp);    float* p_tmp    = (float*)pv;
    cudaGetSymbolAddress(&pv, g_scores); float* p_scores = (float*)pv;
    cudaGetSymbolAddress(&pv, g_gx);     float* p_gxb    = (float*)pv;

    const ll SV = (ll)SEQ * VECT;
    const ll SS = (ll)SEQ * SEQ;
    const float inv_scale = 0.05773502691896258f;   // 1/sqrt(300)

    // dynamic smem for the tf32 mma kernels
    const int SMEM_BT  = 2 * (128 * 36 + 128 * 36) * 4;   // 73728
    const int SMEM_NBT = 2 * (128 * 36 +  32 * 136) * 4;  // 71680
    cudaFuncSetAttribute(mma_gemm<true>,  cudaFuncAttributeMaxDynamicSharedMemorySize, SMEM_BT);
    cudaFuncSetAttribute(mma_gemm<false>, cudaFuncAttributeMaxDynamicSharedMemorySize, SMEM_NBT);

    init_kernel<<<(2 * SEQ * VECT + 255) / 256, 256>>>(x1, x2);

    dim3 gp(5, 64, 2);                 // fp32 projections: N=300 -> 5 tiles of 64
    dim3 gqk(32, 32, 2);               // tf32 QK^T: 4096x4096
    dim3 gav(3, 32, 2);                // tf32 A·V: N=300 -> 3 tiles of 128

    for (int s = 0; s < NSTACK; s++) {
        gemm_kernel<true><<<gp, 256>>>(p_cur, q_w, p_q, SEQ, VECT, VECT, SV, 0, SV, q_b, 1.f);
        gemm_kernel<true><<<gp, 256>>>(p_cur, k_w, p_k, SEQ, VECT, VECT, SV, 0, SV, k_b, 1.f);
        gemm_kernel<true><<<gp, 256>>>(p_cur, v_w, p_v, SEQ, VECT, VECT, SV, 0, SV, v_b, 1.f);

        mma_gemm<true><<<gqk, 256, SMEM_BT>>>(p_q, p_k, p_scores, SEQ, SEQ, VECT,
                                              SV, SV, SS, inv_scale);
        softmax_kernel<<<dim3(SEQ, 2), 256>>>(p_scores);
        mma_gemm<false><<<gav, 256, SMEM_NBT>>>(p_scores, p_v, p_attn, SEQ, VECT, SEQ,
                                                SS, SV, SV, 1.f);

        ln_add_kernel<<<dim3(SEQ / 4, 2), 128>>>(p_attn, p_cur, aln_g, aln_b, p_h);
        gemm_kernel<true><<<gp, 256>>>(p_h, w_w, p_tmp, SEQ, VECT, VECT, SV, 0, SV, w_b, 1.f);
        ln_add_kernel<<<dim3(SEQ / 4, 2), 128>>>(p_tmp, p_x, mln_g, mln_b, p_cur);
    }

    dim3 gg(6, 64, 1);
    gemm_kernel<true><<<gg, 256>>>(p_cur,      g1_wih, p_gxb,            SEQ, G3, VECT,
                                   0, 0, 0, g1_bih, 1.f);
    gemm_kernel<true><<<gg, 256>>>(p_cur + SV, g2_wih, p_gxb + SEQ * G3, SEQ, G3, VECT,
                                   0, 0, 0, g2_bih, 1.f);
    gru_kernel<<<2, 384>>>(g1_whh, g1_bhh, g2_whh, g2_bhh);
    head_kernel<<<1, 256>>>(fc1_w, fc1_b, fc2_w, fc2_b, out);
}

// round 4
// speedup vs baseline: 1.6375x; 1.1956x over previous
#include <cuda_runtime.h>
#include <cstdint>

#define SEQ   4096
#define VECT  300
#define HID   128
#define G3    384
#define NSTACK 3

typedef unsigned long long ull;
typedef long long ll;

// ---------------------------------------------------------------------------
// Scratch (static device globals — allocation-free)
// ---------------------------------------------------------------------------
__device__ float g_x   [2 * SEQ * VECT];
__device__ float g_cur [2 * SEQ * VECT];
__device__ float g_q   [2 * SEQ * VECT];
__device__ float g_k   [2 * SEQ * VECT];
__device__ float g_v   [2 * SEQ * VECT];
__device__ float g_vt  [2 * SEQ * VECT];   // V transposed: [2][VECT][SEQ]
__device__ float g_attn[2 * SEQ * VECT];
__device__ float g_h   [2 * SEQ * VECT];
__device__ float g_tmp [2 * SEQ * VECT];
__device__ float g_scores[2ll * SEQ * SEQ];
__device__ float g_gx  [2 * SEQ * G3];
__device__ float g_hcat[2 * HID];

// ---------------------------------------------------------------------------
__global__ void init_kernel(const float* __restrict__ x1, const float* __restrict__ x2)
{
    int i = blockIdx.x * blockDim.x + threadIdx.x;
    const int n = SEQ * VECT;
    if (i < n) {
        float v = x1[i];
        g_x[i] = v; g_cur[i] = v;
    } else if (i < 2 * n) {
        float v = x2[i - n];
        g_x[i] = v; g_cur[i] = v;
    }
}

// ---------------------------------------------------------------------------
// 32x32 tile transpose: dst[c][r] = src[r][c].  src [SEQ, VECT], dst [VECT, SEQ].
// ---------------------------------------------------------------------------
__global__ __launch_bounds__(256) void transpose_kernel(
    const float* __restrict__ src, float* __restrict__ dst)
{
    __shared__ float t[32][33];
    const ll zo = (ll)blockIdx.z * SEQ * VECT;
    src += zo; dst += zo;
    const int r0 = blockIdx.y * 32, c0 = blockIdx.x * 32;
    const int x = threadIdx.x & 31, y = threadIdx.x >> 5;   // 32 x 8

    #pragma unroll
    for (int i = 0; i < 4; i++) {
        int col = c0 + x;
        if (col < VECT) t[y + 8 * i][x] = src[(size_t)(r0 + y + 8 * i) * VECT + col];
    }
    __syncthreads();
    #pragma unroll
    for (int i = 0; i < 4; i++) {
        int c = c0 + y + 8 * i;
        if (c < VECT) dst[(size_t)c * SEQ + r0 + x] = t[x][y + 8 * i];
    }
}

// ---------------------------------------------------------------------------
// TF32 tensor-core GEMM, B-transposed form only:
//   C[M,N] = alpha * A[M,K] * B[N,K]^T (+ bias[n])
// 128x128x32 tile, cp.async double-buffered, ldmatrix.x4 fragment loads,
// no explicit tf32 cvt (hardware truncation). M % 128 == 0 assumed.
// ---------------------------------------------------------------------------
__device__ __forceinline__ unsigned smem_u32(const void* p)
{
    return (unsigned)__cvta_generic_to_shared(p);
}
__device__ __forceinline__ void cp_async16(unsigned dst, const float* src, bool valid)
{
    int sz = valid ? 16 : 0;
    asm volatile("cp.async.cg.shared.global [%0], [%1], 16, %2;\n"
                 :: "r"(dst), "l"(src), "r"(sz));
}
__device__ __forceinline__ void ldsm_x4(uint32_t* r, unsigned addr)
{
    asm volatile("ldmatrix.sync.aligned.m8n8.x4.shared.b16 {%0,%1,%2,%3}, [%4];"
                 : "=r"(r[0]), "=r"(r[1]), "=r"(r[2]), "=r"(r[3]) : "r"(addr));
}
__device__ __forceinline__ void mma8(float* c, const uint32_t* a, const uint32_t* b)
{
    asm volatile(
        "mma.sync.aligned.m16n8k8.row.col.f32.tf32.tf32.f32 "
        "{%0,%1,%2,%3}, {%4,%5,%6,%7}, {%8,%9}, {%0,%1,%2,%3};"
        : "+f"(c[0]), "+f"(c[1]), "+f"(c[2]), "+f"(c[3])
        : "r"(a[0]), "r"(a[1]), "r"(a[2]), "r"(a[3]), "r"(b[0]), "r"(b[1]));
}

__global__ __launch_bounds__(256) void mma_bt(
    const float* __restrict__ A, const float* __restrict__ B, float* __restrict__ C,
    int M, int N, int K, ll sAb, ll sBb, ll sCb,
    const float* __restrict__ bias, float alpha)
{
    constexpr int BM = 128, BN = 128, BK = 32, AP = 36;
    constexpr int ASZ = BM * AP;          // == BN * AP
    constexpr int STG = 2 * ASZ;          // A + B per stage

    extern __shared__ float sm[];

    A += (ll)blockIdx.z * sAb;
    B += (ll)blockIdx.z * sBb;
    C += (ll)blockIdx.z * sCb;

    const int m0 = blockIdx.y * BM, n0 = blockIdx.x * BN;
    const int tid = threadIdx.x, lane = tid & 31, warp = tid >> 5;
    const int g = lane >> 2, tg = lane & 3;
    const int wm = (warp & 1) * 64, wn = (warp >> 1) * 32;

    // ldmatrix per-lane address components (same pattern for A and B)
    const int lm   = lane >> 3;                     // matrix index 0..3
    const int lrow = (lm & 1) * 8 + (lane & 7);
    const int lcol = (lm >> 1) * 4;

    float acc[4][4][4] = {};
    const int nk = (K + BK - 1) / BK;

    auto load_stage = [&](int s, int k0) {
        unsigned base = smem_u32(sm + s * STG);
        #pragma unroll
        for (int i = 0; i < 4; i++) {
            int idx = tid + i * 256;
            int r = idx >> 3, c = (idx & 7) * 4;
            cp_async16(base + (unsigned)(r * AP + c) * 4,
                       A + (size_t)(m0 + r) * K + k0 + c, (k0 + c < K));
        }
        #pragma unroll
        for (int i = 0; i < 4; i++) {
            int idx = tid + i * 256;
            int r = idx >> 3, c = (idx & 7) * 4;
            bool v = (n0 + r < N) && (k0 + c < K);
            cp_async16(base + (unsigned)(ASZ + r * AP + c) * 4,
                       B + (size_t)(n0 + r) * K + k0 + c, v);
        }
        asm volatile("cp.async.commit_group;");
    };

    load_stage(0, 0);

    for (int kt = 0; kt < nk; kt++) {
        int s = kt & 1;
        if (kt + 1 < nk) {
            load_stage(s ^ 1, (kt + 1) * BK);
            asm volatile("cp.async.wait_group 1;");
        } else {
            asm volatile("cp.async.wait_group 0;");
        }
        __syncthreads();

        unsigned aBase = smem_u32(sm + s * STG)
                       + (unsigned)((wm + lrow) * AP + lcol) * 4;
        unsigned bBase = smem_u32(sm + s * STG + ASZ)
                       + (unsigned)((wn + lrow) * AP + lcol) * 4;

        #pragma unroll
        for (int kk = 0; kk < BK; kk += 8) {
            uint32_t ar[4][4];
            #pragma unroll
            for (int mt = 0; mt < 4; mt++)
                ldsm_x4(ar[mt], aBase + (unsigned)(mt * 16 * AP + kk) * 4);
            uint32_t brq[2][4];
            #pragma unroll
            for (int nh = 0; nh < 2; nh++)
                ldsm_x4(brq[nh], bBase + (unsigned)(nh * 16 * AP + kk) * 4);

            #pragma unroll
            for (int mt = 0; mt < 4; mt++) {
                #pragma unroll
                for (int nt = 0; nt < 4; nt++) {
                    uint32_t bb[2] = { brq[nt >> 1][nt & 1], brq[nt >> 1][(nt & 1) + 2] };
                    mma8(acc[mt][nt], ar[mt], bb);
                }
            }
        }
        __syncthreads();
    }

    #pragma unroll
    for (int mt = 0; mt < 4; mt++) {
        #pragma unroll
        for (int nt = 0; nt < 4; nt++) {
            int row0 = m0 + wm + mt * 16 + g;
            int col  = n0 + wn + nt * 8 + 2 * tg;
            if (col + 1 < N) {
                float b0 = bias ? bias[col]     : 0.f;
                float b1 = bias ? bias[col + 1] : 0.f;
                float2 v0 = make_float2(alpha * acc[mt][nt][0] + b0,
                                        alpha * acc[mt][nt][1] + b1);
                float2 v1 = make_float2(alpha * acc[mt][nt][2] + b0,
                                        alpha * acc[mt][nt][3] + b1);
                *reinterpret_cast<float2*>(C + (size_t)row0 * N + col) = v0;
                *reinterpret_cast<float2*>(C + (size_t)(row0 + 8) * N + col) = v1;
            } else if (col < N) {
                float b0 = bias ? bias[col] : 0.f;
                C[(size_t)row0 * N + col]       = alpha * acc[mt][nt][0] + b0;
                C[(size_t)(row0 + 8) * N + col] = alpha * acc[mt][nt][2] + b0;
            }
        }
    }
}

// ---------------------------------------------------------------------------
__device__ __forceinline__ float warp_max(float v) {
    #pragma unroll
    for (int o = 16; o > 0; o >>= 1) v = fmaxf(v, __shfl_xor_sync(0xffffffffu, v, o));
    return v;
}
__device__ __forceinline__ float warp_sum(float v) {
    #pragma unroll
    for (int o = 16; o > 0; o >>= 1) v += __shfl_xor_sync(0xffffffffu, v, o);
    return v;
}

__global__ __launch_bounds__(256) void softmax_kernel(float* __restrict__ Sm)
{
    size_t off = ((size_t)blockIdx.y * SEQ + blockIdx.x) * SEQ;
    float4* row4 = reinterpret_cast<float4*>(Sm + off);
    const int t = threadIdx.x;
    const int lane = t & 31, wid = t >> 5;

    float4 v[4];
    #pragma unroll
    for (int i = 0; i < 4; i++) v[i] = row4[t + 256 * i];

    float m = -3.4e38f;
    #pragma unroll
    for (int i = 0; i < 4; i++)
        m = fmaxf(m, fmaxf(fmaxf(v[i].x, v[i].y), fmaxf(v[i].z, v[i].w)));

    __shared__ float red[8];
    m = warp_max(m);
    if (lane == 0) red[wid] = m;
    __syncthreads();
    float bm = red[0];
    #pragma unroll
    for (int k = 1; k < 8; k++) bm = fmaxf(bm, red[k]);

    float s = 0.f;
    #pragma unroll
    for (int i = 0; i < 4; i++) {
        v[i].x = __expf(v[i].x - bm); v[i].y = __expf(v[i].y - bm);
        v[i].z = __expf(v[i].z - bm); v[i].w = __expf(v[i].w - bm);
        s += v[i].x + v[i].y + v[i].z + v[i].w;
    }
    s = warp_sum(s);
    __syncthreads();
    if (lane == 0) red[wid] = s;
    __syncthreads();
    float bs = 0.f;
    #pragma unroll
    for (int k = 0; k < 8; k++) bs += red[k];
    float inv = 1.f / bs;

    #pragma unroll
    for (int i = 0; i < 4; i++) {
        v[i].x *= inv; v[i].y *= inv; v[i].z *= inv; v[i].w *= inv;
        row4[t + 256 * i] = v[i];
    }
}

// ---------------------------------------------------------------------------
__global__ __launch_bounds__(128) void ln_add_kernel(
    const float* __restrict__ s1, const float* __restrict__ s2,
    const float* __restrict__ g, const float* __restrict__ b,
    float* __restrict__ dst)
{
    const int wid = threadIdx.x >> 5, lane = threadIdx.x & 31;
    const int row = blockIdx.x * 4 + wid;
    const size_t base = ((size_t)blockIdx.y * SEQ + row) * VECT;

    float v[10];
    float s = 0.f;
    #pragma unroll
    for (int i = 0; i < 10; i++) {
        int j = lane + 32 * i;
        float x = 0.f;
        if (j < VECT) x = s1[base + j] + s2[base + j];
        v[i] = x; s += x;
    }
    s = warp_sum(s);
    float mean = s * (1.f / VECT);

    float var = 0.f;
    #pragma unroll
    for (int i = 0; i < 10; i++) {
        int j = lane + 32 * i;
        if (j < VECT) { float d = v[i] - mean; var += d * d; }
    }
    var = warp_sum(var) * (1.f / VECT);
    float inv = rsqrtf(var + 1e-5f);

    #pragma unroll
    for (int i = 0; i < 10; i++) {
        int j = lane + 32 * i;
        if (j < VECT) dst[base + j] = g[j] * (v[i] - mean) * inv + b[j];
    }
}

// ---------------------------------------------------------------------------
__global__ __launch_bounds__(384, 1) void gru_kernel(
    const float* __restrict__ whh1, const float* __restrict__ bhh1,
    const float* __restrict__ whh2, const float* __restrict__ bhh2)
{
    const int b = blockIdx.x;
    const float* whh = b ? whh2 : whh1;
    const float* bhh = b ? bhh2 : bhh1;
    const float* gx  = g_gx + (size_t)b * SEQ * G3;
    const int t = threadIdx.x;

    ull wp[64];
    const ull* w2 = reinterpret_cast<const ull*>(whh + t * HID);
    #pragma unroll
    for (int j = 0; j < 64; j++) wp[j] = w2[j];
    const float bh = bhh[t];

    __shared__ __align__(16) float hsh[HID];
    __shared__ float gsh[G3];
    float hcur = 0.f;
    if (t < HID) hsh[t] = 0.f;
    __syncthreads();

    for (int step = 0; step < SEQ; step++) {
        float xr = 0.f, xz = 0.f, xn = 0.f;
        if (t < HID) {
            const float* gr = gx + (size_t)step * G3;
            xr = gr[t]; xz = gr[t + HID]; xn = gr[t + 2 * HID];
        }

        ull a0 = 0ull, a1 = 0ull;
        const ulonglong2* h2 = reinterpret_cast<const ulonglong2*>(hsh);
        #pragma unroll
        for (int j = 0; j < 32; j++) {
            ulonglong2 hv = h2[j];
            asm("fma.rn.f32x2 %0, %1, %2, %0;" : "+l"(a0) : "l"(wp[2 * j]),     "l"(hv.x));
            asm("fma.rn.f32x2 %0, %1, %2, %0;" : "+l"(a1) : "l"(wp[2 * j + 1]), "l"(hv.y));
        }
        float lo0, hi0, lo1, hi1;
        asm("mov.b64 {%0,%1}, %2;" : "=f"(lo0), "=f"(hi0) : "l"(a0));
        asm("mov.b64 {%0,%1}, %2;" : "=f"(lo1), "=f"(hi1) : "l"(a1));
        gsh[t] = lo0 + hi0 + lo1 + hi1 + bh;
        __syncthreads();

        if (t < HID) {
            float r = 1.f / (1.f + __expf(-(xr + gsh[t])));
            float z = 1.f / (1.f + __expf(-(xz + gsh[t + HID])));
            float n = tanhf(xn + r * gsh[t + 2 * HID]);
            hcur = (1.f - z) * n + z * hcur;
            hsh[t] = hcur;
        }
        __syncthreads();
    }
    if (t < HID) g_hcat[b * HID + t] = hcur;
}

// ---------------------------------------------------------------------------
__global__ __launch_bounds__(256) void head_kernel(
    const float* __restrict__ fc1_w, const float* __restrict__ fc1_b,
    const float* __restrict__ fc2_w, const float* __restrict__ fc2_b,
    float* __restrict__ out)
{
    __shared__ float hs[256], ys[256], ls[3];
    const int t = threadIdx.x;
    hs[t] = g_hcat[t];
    __syncthreads();

    float acc = fc1_b[t];
    #pragma unroll 8
    for (int j = 0; j < 256; j++) acc += fc1_w[t * 256 + j] * hs[j];
    ys[t] = fmaxf(acc, 0.f);
    __syncthreads();

    if (t < 3) {
        float a = fc2_b[t];
        for (int j = 0; j < 256; j++) a += fc2_w[t * 256 + j] * ys[j];
        ls[t] = a;
    }
    __syncthreads();

    if (t == 0) {
        float m = fmaxf(ls[0], fmaxf(ls[1], ls[2]));
        float s = expf(ls[0] - m) + expf(ls[1] - m) + expf(ls[2] - m);
        float lse = m + logf(s);
        out[0] = ls[0] - lse; out[1] = ls[1] - lse; out[2] = ls[2] - lse;
    }
}

// ---------------------------------------------------------------------------
extern "C" void kernel_launch(void* const* d_in, const int* in_sizes, int n_in,
                              void* d_out, int out_size)
{
    (void)in_sizes; (void)n_in; (void)out_size;

    const float* x1     = (const float*)d_in[0];
    const float* x2     = (const float*)d_in[1];
    const float* q_w    = (const float*)d_in[2];
    const float* q_b    = (const float*)d_in[3];
    const float* k_w    = (const float*)d_in[4];
    const float* k_b    = (const float*)d_in[5];
    const float* v_w    = (const float*)d_in[6];
    const float* v_b    = (const float*)d_in[7];
    const float* aln_g  = (const float*)d_in[8];
    const float* aln_b  = (const float*)d_in[9];
    const float* w_w    = (const float*)d_in[10];
    const float* w_b    = (const float*)d_in[11];
    const float* mln_g  = (const float*)d_in[12];
    const float* mln_b  = (const float*)d_in[13];
    const float* g1_wih = (const float*)d_in[14];
    const float* g1_whh = (const float*)d_in[15];
    const float* g1_bih = (const float*)d_in[16];
    const float* g1_bhh = (const float*)d_in[17];
    const float* g2_wih = (const float*)d_in[18];
    const float* g2_whh = (const float*)d_in[19];
    const float* g2_bih = (const float*)d_in[20];
    const float* g2_bhh = (const float*)d_in[21];
    const float* fc1_w  = (const float*)d_in[22];
    const float* fc1_b  = (const float*)d_in[23];
    const float* fc2_w  = (const float*)d_in[24];
    const float* fc2_b  = (const float*)d_in[25];
    float* out = (float*)d_out;

    void *pv;
    cudaGetSymbolAddress(&pv, g_x);      float* p_x      = (float*)pv;
    cudaGetSymbolAddress(&pv, g_cur);    float* p_cur    = (float*)pv;
    cudaGetSymbolAddress(&pv, g_q);      float* p_q      = (float*)pv;
    cudaGetSymbolAddress(&pv, g_k);      float* p_k      = (float*)pv;
    cudaGetSymbolAddress(&pv, g_v);      float* p_v      = (float*)pv;
    cudaGetSymbolAddress(&pv, g_vt);     float* p_vt     = (float*)pv;
    cudaGetSymbolAddress(&pv, g_attn);   float* p_attn   = (float*)pv;
    cudaGetSymbolAddress(&pv, g_h);      float* p_h      = (float*)pv;
    cudaGetSymbolAddress(&pv, g_tmp);    float* p_tmp    = (float*)pv;
    cudaGetSymbolAddress(&pv, g_scores); float* p_scores = (float*)pv;
    cudaGetSymbolAddress(&pv, g_gx);     float* p_gxb    = (float*)pv;

    const ll SV = (ll)SEQ * VECT;
    const ll SS = (ll)SEQ * SEQ;
    const float inv_scale = 0.05773502691896258f;   // 1/sqrt(300)

    const int SMEM_MMA = 2 * (128 * 36 + 128 * 36) * 4;   // 73728
    cudaFuncSetAttribute(mma_bt, cudaFuncAttributeMaxDynamicSharedMemorySize, SMEM_MMA);

    init_kernel<<<(2 * SEQ * VECT + 255) / 256, 256>>>(x1, x2);

    dim3 gp(3, 32, 2);                 // N=300 -> 3 tiles of 128
    dim3 gqk(32, 32, 2);               // QK^T: 4096x4096
    dim3 gtr(10, 128, 2);              // V transpose

    for (int s = 0; s < NSTACK; s++) {
        mma_bt<<<gp, 256, SMEM_MMA>>>(p_cur, q_w, p_q, SEQ, VECT, VECT, SV, 0, SV, q_b, 1.f);
        mma_bt<<<gp, 256, SMEM_MMA>>>(p_cur, k_w, p_k, SEQ, VECT, VECT, SV, 0, SV, k_b, 1.f);
        mma_bt<<<gp, 256, SMEM_MMA>>>(p_cur, v_w, p_v, SEQ, VECT, VECT, SV, 0, SV, v_b, 1.f);

        mma_bt<<<gqk, 256, SMEM_MMA>>>(p_q, p_k, p_scores, SEQ, SEQ, VECT,
                                       SV, SV, SS, nullptr, inv_scale);
        softmax_kernel<<<dim3(SEQ, 2), 256>>>(p_scores);

        transpose_kernel<<<gtr, 256>>>(p_v, p_vt);
        mma_bt<<<gp, 256, SMEM_MMA>>>(p_scores, p_vt, p_attn, SEQ, VECT, SEQ,
                                      SS, SV, SV, nullptr, 1.f);

        ln_add_kernel<<<dim3(SEQ / 4, 2), 128>>>(p_attn, p_cur, aln_g, aln_b, p_h);
        mma_bt<<<gp, 256, SMEM_MMA>>>(p_h, w_w, p_tmp, SEQ, VECT, VECT, SV, 0, SV, w_b, 1.f);
        ln_add_kernel<<<dim3(SEQ / 4, 2), 128>>>(p_tmp, p_x, mln_g, mln_b, p_cur);
    }

    dim3 gg(3, 32, 1);                 // N=384 -> 3 tiles of 128
    mma_bt<<<gg, 256, SMEM_MMA>>>(p_cur,      g1_wih, p_gxb,            SEQ, G3, VECT,
                                  0, 0, 0, g1_bih, 1.f);
    mma_bt<<<gg, 256, SMEM_MMA>>>(p_cur + SV, g2_wih, p_gxb + SEQ * G3, SEQ, G3, VECT,
                                  0, 0, 0, g2_bih, 1.f);
    gru_kernel<<<2, 384>>>(g1_whh, g1_bhh, g2_whh, g2_bhh);
    head_kernel<<<1, 256>>>(fc1_w, fc1_b, fc2_w, fc2_b, out);
}